// round 2
// baseline (speedup 1.0000x reference)
#include <cuda_runtime.h>
#include <cuda_bf16.h>
#include <math.h>

// Problem shape constants (fixed by the reference).
#define B_DIM 8192
#define S_DIM 10
#define H_DIM 1024
#define ALPHA_ROWS (2700 * 6)   // 16200
#define ALPHA_COLS 10
#define MARGIN_EPS 0.5f
#define PD_EPS 1e-6f
#define SENTINEL 10.0f

#define THREADS 256
#define ALPHA_BLOCKS 64

// Scratch (device globals: allocation-free per the harness rules).
__device__ float g_margin_partial[B_DIM];     // per-batch-row margin contribution
__device__ float g_alpha_partial[ALPHA_BLOCKS];

// ---------------------------------------------------------------------------
// Kernel 1: per-batch-row margin contribution.
// One CTA per row. 256 threads x float4 = 1024 floats per row slice.
// all_gloss is streamed once -> evict-first loads (__ldcs).
// ---------------------------------------------------------------------------
__global__ __launch_bounds__(THREADS, 4)
void margin_kernel(const float* __restrict__ sentence,
                   const float* __restrict__ all_gloss,
                   const int*   __restrict__ sense_mask,
                   const int*   __restrict__ sense_ids)
{
    const int b    = blockIdx.x;
    const int tid  = threadIdx.x;
    const int lane = tid & 31;
    const int wid  = tid >> 5;

    __shared__ float s_warp[8][S_DIM];   // per-warp partial SSQs
    __shared__ float s_d[S_DIM];         // final distances

    // Sentence slice in registers (coalesced float4).
    const float4* srow = reinterpret_cast<const float4*>(sentence + (size_t)b * H_DIM);
    const float4 xs = __ldg(&srow[tid]);

    // Stream 10 gloss rows; accumulate per-thread SSQ for each sense.
    // Unrolled s-loop gives MLP=10 independent 16B loads in flight per thread.
    float acc[S_DIM];
    const float4* grow = reinterpret_cast<const float4*>(all_gloss + (size_t)b * S_DIM * H_DIM);

    #pragma unroll
    for (int s = 0; s < S_DIM; s++) {
        float4 y = __ldcs(&grow[s * (H_DIM / 4) + tid]);
        float dx = xs.x - y.x + PD_EPS;
        float dy = xs.y - y.y + PD_EPS;
        float dz = xs.z - y.z + PD_EPS;
        float dw = xs.w - y.w + PD_EPS;
        acc[s] = dx * dx + dy * dy + dz * dz + dw * dw;
    }

    // Warp reduce all 10 accumulators.
    #pragma unroll
    for (int s = 0; s < S_DIM; s++) {
        float v = acc[s];
        #pragma unroll
        for (int off = 16; off > 0; off >>= 1)
            v += __shfl_down_sync(0xFFFFFFFFu, v, off);
        if (lane == 0) s_warp[wid][s] = v;
    }
    __syncthreads();

    // Threads 0..9 each finalize one distance (sum 8 warp partials, fixed order).
    if (tid < S_DIM) {
        float v = 0.0f;
        #pragma unroll
        for (int w = 0; w < 8; w++) v += s_warp[w][tid];
        s_d[tid] = sqrtf(v);
    }
    __syncthreads();

    if (tid == 0) {
        const int sid = __ldg(&sense_ids[b]);
        const float pos = s_d[sid];

        // Hard-negative argmin over masked distances (ties -> first index).
        const int* mrow = sense_mask + (size_t)b * S_DIM;
        float best = 1e30f;
        int best_idx = 0;
        #pragma unroll
        for (int s = 0; s < S_DIM; s++) {
            bool valid = (__ldg(&mrow[s]) != 0) && (s != sid);
            float m = valid ? s_d[s] : SENTINEL;
            if (m < best) { best = m; best_idx = s; }
        }
        // Reference recomputes pdist on the gathered gloss => equals d[best_idx]
        // (sentinel never leaks into neg, even when no sense is valid).
        const float neg = s_d[best_idx];
        g_margin_partial[b] = fmaxf(pos - neg + MARGIN_EPS, 0.0f);
    }
}

// ---------------------------------------------------------------------------
// Kernel 2: alpha term partials. 16200 rows x 10 cols, tiny (648 KB).
// ---------------------------------------------------------------------------
__global__ __launch_bounds__(THREADS)
void alpha_kernel(const float* __restrict__ alpha)
{
    const int tid = threadIdx.x;
    __shared__ float s_red[THREADS];

    float local = 0.0f;
    for (int r = blockIdx.x * THREADS + tid; r < ALPHA_ROWS;
         r += ALPHA_BLOCKS * THREADS) {
        const float* row = alpha + (size_t)r * ALPHA_COLS;
        float rsum = 0.0f, rmax = -1e30f;
        #pragma unroll
        for (int c = 0; c < ALPHA_COLS; c++) {
            float v = __ldg(&row[c]);
            rsum += v;
            rmax = fmaxf(rmax, v);
        }
        // row_sum == 0 -> tmp = ones -> max = 1 -> |1-1| = 0
        local += (rsum == 0.0f) ? 0.0f : fabsf(rmax - 1.0f);
    }

    s_red[tid] = local;
    __syncthreads();
    #pragma unroll
    for (int off = THREADS / 2; off > 0; off >>= 1) {
        if (tid < off) s_red[tid] += s_red[tid + off];
        __syncthreads();
    }
    if (tid == 0) g_alpha_partial[blockIdx.x] = s_red[0];
}

// ---------------------------------------------------------------------------
// Kernel 3: deterministic final reduction -> [loss, margin, alpha_term].
// ---------------------------------------------------------------------------
__global__ __launch_bounds__(THREADS)
void final_kernel(float* __restrict__ out, int out_size)
{
    const int tid = threadIdx.x;
    __shared__ float s_m[THREADS];
    __shared__ float s_a[THREADS];

    // Fixed-order per-thread strided sums (deterministic across graph replays).
    float m = 0.0f;
    for (int i = tid; i < B_DIM; i += THREADS) m += g_margin_partial[i];
    float a = 0.0f;
    for (int i = tid; i < ALPHA_BLOCKS; i += THREADS) a += g_alpha_partial[i];

    s_m[tid] = m;
    s_a[tid] = a;
    __syncthreads();
    #pragma unroll
    for (int off = THREADS / 2; off > 0; off >>= 1) {
        if (tid < off) { s_m[tid] += s_m[tid + off]; s_a[tid] += s_a[tid + off]; }
        __syncthreads();
    }

    if (tid == 0) {
        float margin = s_m[0];
        float alpha_term = s_a[0];
        float loss = margin * 0.875f + alpha_term * 0.125f;
        if (out_size >= 1) out[0] = loss;
        if (out_size >= 2) out[1] = margin;
        if (out_size >= 3) out[2] = alpha_term;
    }
}

// ---------------------------------------------------------------------------
extern "C" void kernel_launch(void* const* d_in, const int* in_sizes, int n_in,
                              void* d_out, int out_size)
{
    const float* sentence   = (const float*)d_in[0];  // (B, H) f32
    const float* all_gloss  = (const float*)d_in[1];  // (B, S, H) f32
    const float* alpha      = (const float*)d_in[2];  // (2700, 6, 10) f32
    const int*   sense_mask = (const int*)d_in[3];    // (B, S) i32
    const int*   sense_ids  = (const int*)d_in[4];    // (B,) i32

    margin_kernel<<<B_DIM, THREADS>>>(sentence, all_gloss, sense_mask, sense_ids);
    alpha_kernel<<<ALPHA_BLOCKS, THREADS>>>(alpha);
    final_kernel<<<1, THREADS>>>((float*)d_out, out_size);
}